// round 15
// baseline (speedup 1.0000x reference)
#include <cuda_runtime.h>
#include <math.h>
#include <stdint.h>

#define NB     4
#define SEQ    2048
#define DMODEL 512
#define NH     8
#define DKH    64
#define FDIM   2048
#define MROWS  (NB*SEQ)   // 8192
#define QKVN   1536

// -------- scratch (device globals; no allocation allowed) --------
__device__ float g_h   [MROWS*DMODEL];
__device__ float g_qkv [MROWS*QKVN];
__device__ float g_ctx [MROWS*DMODEL];
__device__ float g_x1  [MROWS*DMODEL];
__device__ float g_h2  [MROWS*DMODEL];
__device__ float g_ff  [MROWS*FDIM];
__device__ float g_wqkv[QKVN*DMODEL];
__device__ float g_bqkv[QKVN];

// ================= helpers =================
__device__ __forceinline__ uint32_t smem_u32(const void* p) {
    uint32_t a;
    asm("{ .reg .u64 t; cvta.to.shared.u64 t, %1; cvt.u32.u64 %0, t; }" : "=r"(a) : "l"(p));
    return a;
}
__device__ __forceinline__ void cp16(uint32_t dst, const void* src) {
    asm volatile("cp.async.cg.shared.global [%0], [%1], 16;" :: "r"(dst), "l"(src) : "memory");
}
__device__ __forceinline__ uint32_t f2r(float f) { return __float_as_uint(f); }
__device__ __forceinline__ void mma_tf32(float* c, const uint32_t* a, const uint32_t* b) {
    asm volatile("mma.sync.aligned.m16n8k8.row.col.f32.tf32.tf32.f32 "
        "{%0,%1,%2,%3}, {%4,%5,%6,%7}, {%8,%9}, {%0,%1,%2,%3};"
        : "+f"(c[0]), "+f"(c[1]), "+f"(c[2]), "+f"(c[3])
        : "r"(a[0]), "r"(a[1]), "r"(a[2]), "r"(a[3]), "r"(b[0]), "r"(b[1]));
}
#define LDSM4(R, addr) asm volatile( \
    "ldmatrix.sync.aligned.m8n8.x4.shared.b16 {%0,%1,%2,%3}, [%4];" \
    : "=r"((R)[0]), "=r"((R)[1]), "=r"((R)[2]), "=r"((R)[3]) : "r"(addr))
#define CP_COMMIT()  asm volatile("cp.async.commit_group;" ::: "memory")
#define CP_WAIT0()   asm volatile("cp.async.wait_group 0;" ::: "memory")

// ================= weight pack =================
__global__ __launch_bounds__(128) void pack_qkv(const float* __restrict__ wq,
                                                const float* __restrict__ wk,
                                                const float* __restrict__ wv,
                                                const float* __restrict__ bq,
                                                const float* __restrict__ bk,
                                                const float* __restrict__ bv) {
    int r = blockIdx.x;
    const float* src = (r < 512) ? (wq + (size_t)r * DMODEL)
                     : (r < 1024) ? (wk + (size_t)(r - 512) * DMODEL)
                                  : (wv + (size_t)(r - 1024) * DMODEL);
    float4 vv = ((const float4*)src)[threadIdx.x];
    ((float4*)(g_wqkv + (size_t)r * DMODEL))[threadIdx.x] = vv;
    if (threadIdx.x == 0) {
        g_bqkv[r] = (r < 512) ? bq[r] : (r < 1024) ? bk[r - 512] : bv[r - 1024];
    }
}

// ================= LayerNorm (torch semantics), warp-per-row =================
__global__ __launch_bounds__(128) void ln_k(const float* __restrict__ x,
                                            float* __restrict__ out,
                                            const float* __restrict__ alpha,
                                            const float* __restrict__ beta) {
    int row = blockIdx.x * 4 + (threadIdx.x >> 5);
    int lane = threadIdx.x & 31;
    const float4* xr = (const float4*)(x + (size_t)row * DMODEL);
    float4 v[4];
    #pragma unroll
    for (int i = 0; i < 4; i++) v[i] = xr[lane + 32 * i];
    float s = 0.f;
    #pragma unroll
    for (int i = 0; i < 4; i++) s += v[i].x + v[i].y + v[i].z + v[i].w;
    #pragma unroll
    for (int o = 16; o; o >>= 1) s += __shfl_xor_sync(0xffffffffu, s, o);
    float mean = s * (1.f / DMODEL);
    float ss = 0.f;
    #pragma unroll
    for (int i = 0; i < 4; i++) {
        v[i].x -= mean; v[i].y -= mean; v[i].z -= mean; v[i].w -= mean;
        ss += v[i].x * v[i].x + v[i].y * v[i].y + v[i].z * v[i].z + v[i].w * v[i].w;
    }
    #pragma unroll
    for (int o = 16; o; o >>= 1) ss += __shfl_xor_sync(0xffffffffu, ss, o);
    float var = ss * (1.f / (DMODEL - 1));
    float inv = 1.f / (sqrtf(var) + 1e-6f);
    float a = alpha[0], b = beta[0];
    float4* orow = (float4*)(out + (size_t)row * DMODEL);
    #pragma unroll
    for (int i = 0; i < 4; i++) {
        float4 o4;
        o4.x = a * v[i].x * inv + b;
        o4.y = a * v[i].y * inv + b;
        o4.z = a * v[i].z * inv + b;
        o4.w = a * v[i].w * inv + b;
        orow[lane + 32 * i] = o4;
    }
}

// ================= tf32 warp-MMA GEMM 128x128 (proven, 2-stage) =================
#define GROW 36
#define ATILE_B (128 * GROW * 4)
#define STAGE_B (2 * ATILE_B)
#define GEMM_SMEM (2 * STAGE_B)

template<int RELU, int RES>
__global__ __launch_bounds__(256) void gemm_mma(const float* __restrict__ A,
                                                const float* __restrict__ B,
                                                const float* __restrict__ bias,
                                                const float* __restrict__ res,
                                                float* __restrict__ C,
                                                int M, int N, int K) {
    extern __shared__ char smem[];
    uint32_t sb = smem_u32(smem);
    int tid = threadIdx.x, wid = tid >> 5, lane = tid & 31;
    int gr = lane >> 2, gc = lane & 3;
    int g = lane >> 3;
    int wm = (wid >> 2) * 64, wn = (wid & 3) * 32;
    int bm = blockIdx.y * 128, bn = blockIdx.x * 128;

    const float* Abase = A + (size_t)bm * K;
    const float* Bbase = B + (size_t)bn * K;

    uint32_t a_lane = (uint32_t)((wm + (g & 1) * 8 + (lane & 7)) * GROW + (g >> 1) * 4);
    uint32_t b_lane = (uint32_t)((wn + (lane & 7) + ((lane >> 4) & 1) * 8) * GROW + ((lane >> 3) & 1) * 4);

    float acc[4][4][4];
    #pragma unroll
    for (int i = 0; i < 4; i++)
        #pragma unroll
        for (int j = 0; j < 4; j++)
            #pragma unroll
            for (int r = 0; r < 4; r++) acc[i][j][r] = 0.f;

    int lrow = tid >> 3, lc4 = tid & 7;

    auto load_chunk = [&](int c, int s) {
        uint32_t ab = sb + s * STAGE_B;
        uint32_t bb = ab + ATILE_B;
        const float* Ap = Abase + c * 32;
        const float* Bp = Bbase + c * 32;
        #pragma unroll
        for (int i = 0; i < 4; i++) {
            int row = i * 32 + lrow;
            uint32_t off = (uint32_t)(row * (GROW * 4) + lc4 * 16);
            cp16(ab + off, Ap + (size_t)row * K + lc4 * 4);
            cp16(bb + off, Bp + (size_t)row * K + lc4 * 4);
        }
    };

    const int NC = K / 32;
    load_chunk(0, 0);
    CP_COMMIT();
    CP_WAIT0();
    __syncthreads();

    int buf = 0;
    for (int ch = 0; ch < NC; ch++) {
        if (ch + 1 < NC) {
            load_chunk(ch + 1, buf ^ 1);
            CP_COMMIT();
        }
        uint32_t ab = sb + buf * STAGE_B + a_lane * 4;
        uint32_t bb = sb + buf * STAGE_B + ATILE_B + b_lane * 4;
        #pragma unroll
        for (int ks = 0; ks < 4; ks++) {
            uint32_t ar[4][4];
            #pragma unroll
            for (int i = 0; i < 4; i++)
                LDSM4(ar[i], ab + (uint32_t)((i * 16 * GROW + ks * 8) * 4));
            uint32_t br[2][4];
            #pragma unroll
            for (int p = 0; p < 2; p++)
                LDSM4(br[p], bb + (uint32_t)((p * 16 * GROW + ks * 8) * 4));
            #pragma unroll
            for (int i = 0; i < 4; i++)
                #pragma unroll
                for (int j = 0; j < 4; j++)
                    mma_tf32(acc[i][j], ar[i], &br[j >> 1][(j & 1) * 2]);
        }
        if (ch + 1 < NC)
            CP_WAIT0();
        __syncthreads();
        buf ^= 1;
    }

    #pragma unroll
    for (int i = 0; i < 4; i++) {
        int row0 = bm + wm + i * 16 + gr;
        #pragma unroll
        for (int j = 0; j < 4; j++) {
            int col = bn + wn + j * 8 + 2 * gc;
            float2 b2 = *(const float2*)&bias[col];
            float2 v0, v1;
            v0.x = acc[i][j][0] + b2.x; v0.y = acc[i][j][1] + b2.y;
            v1.x = acc[i][j][2] + b2.x; v1.y = acc[i][j][3] + b2.y;
            if (RELU) {
                v0.x = fmaxf(v0.x, 0.f); v0.y = fmaxf(v0.y, 0.f);
                v1.x = fmaxf(v1.x, 0.f); v1.y = fmaxf(v1.y, 0.f);
            }
            if (RES) {
                float2 r0 = *(const float2*)&res[(size_t)row0 * N + col];
                float2 r1 = *(const float2*)&res[(size_t)(row0 + 8) * N + col];
                v0.x += r0.x; v0.y += r0.y;
                v1.x += r1.x; v1.y += r1.y;
            }
            *(float2*)&C[(size_t)row0 * N + col] = v0;
            *(float2*)&C[(size_t)(row0 + 8) * N + col] = v1;
        }
    }
}

// ================= tf32 warp-MMA flash attention: 4 warps x 32 queries, 3 CTAs/SM =================
// QK computed per query-block sequentially (s[8][4] reused) to fit the 170-reg budget.
#define APAD 68
#define AT_KS   0
#define AT_VT   (64 * APAD)
#define AT_MADD (2 * 64 * APAD)
#define AT_PS   (2 * 64 * APAD + 64)
#define ATTN_SMEM ((2 * 64 * APAD + 64 + 4 * 32 * APAD) * 4)

__global__ __launch_bounds__(128, 3) void attn_mma(const float* __restrict__ QKV,
                                                   const int* __restrict__ mask,
                                                   float* __restrict__ O) {
    extern __shared__ float sm[];
    uint32_t sb = smem_u32(sm);
    float* VT   = sm + AT_VT;
    float* madd = sm + AT_MADD;

    int tid = threadIdx.x, wid = tid >> 5, lane = tid & 31;
    int gr = lane >> 2, gc = lane & 3;
    int g = lane >> 3;
    int bh = blockIdx.x, b = bh >> 3, hh = bh & 7;
    int q0 = blockIdx.y * 128;
    int wrow = wid * 32;

    const int LD = QKVN;
    const float* Qb = QKV + ((size_t)b * SEQ + q0) * LD + hh * DKH;
    const float* Kb = QKV + (size_t)b * SEQ * LD + 512 + hh * DKH;
    const float* Vb = QKV + (size_t)b * SEQ * LD + 1024 + hh * DKH;
    float* Pw = sm + AT_PS + wid * 32 * APAD;

    uint32_t bk_lane = (uint32_t)(((lane & 7) + ((lane >> 4) & 1) * 8) * APAD + ((lane >> 3) & 1) * 4);
    uint32_t pa_lane = (uint32_t)(((g & 1) * 8 + (lane & 7)) * APAD + (g >> 1) * 4);
    uint32_t ksb = sb + AT_KS * 4 + bk_lane * 4;
    uint32_t vtb = sb + AT_VT * 4 + bk_lane * 4;
    uint32_t pwb = sb + (AT_PS + wid * 32 * APAD) * 4 + pa_lane * 4;

    // Q fragments for 2 query blocks of 16 rows (pre-scaled by 1/8)
    uint32_t qa[2][8][4];
    #pragma unroll
    for (int qb = 0; qb < 2; qb++)
        #pragma unroll
        for (int ks = 0; ks < 8; ks++) {
            int r0 = wrow + qb * 16 + gr, c0 = ks * 8 + gc;
            qa[qb][ks][0] = f2r(Qb[(size_t)r0 * LD + c0] * 0.125f);
            qa[qb][ks][1] = f2r(Qb[(size_t)(r0 + 8) * LD + c0] * 0.125f);
            qa[qb][ks][2] = f2r(Qb[(size_t)r0 * LD + c0 + 4] * 0.125f);
            qa[qb][ks][3] = f2r(Qb[(size_t)(r0 + 8) * LD + c0 + 4] * 0.125f);
        }

    float o[2][8][4];
    #pragma unroll
    for (int qb = 0; qb < 2; qb++)
        #pragma unroll
        for (int j = 0; j < 8; j++)
            #pragma unroll
            for (int r = 0; r < 4; r++) o[qb][j][r] = 0.f;
    float lsum[2][2] = {{0.f, 0.f}, {0.f, 0.f}};

    int vd = tid & 63, vk4 = (tid >> 6) * 32;
    for (int kt = 0; kt < SEQ; kt += 64) {
        __syncthreads();
        // K tile -> Ks[key][dim]
        #pragma unroll
        for (int i = 0; i < 8; i++) {
            int li = i * 128 + tid;
            int row = li >> 4, c16 = li & 15;
            cp16(sb + (uint32_t)((AT_KS + row * APAD + c16 * 4) * 4),
                 Kb + (size_t)(kt + row) * LD + c16 * 4);
        }
        CP_COMMIT();
        // V tile transposed -> VT[dim][key]
        #pragma unroll
        for (int i = 0; i < 32; i++) {
            VT[vd * APAD + vk4 + i] = __ldg(&Vb[(size_t)(kt + vk4 + i) * LD + vd]);
        }
        if (tid < 64)
            madd[tid] = (mask[b * SEQ + kt + tid] == 0) ? -1e9f : 0.f;
        CP_WAIT0();
        __syncthreads();

        // ---- per query-block: S = Q K^T, exp, P to smem (s reused) ----
        #pragma unroll
        for (int qb = 0; qb < 2; qb++) {
            float s[8][4];
            #pragma unroll
            for (int j = 0; j < 8; j++)
                #pragma unroll
                for (int r = 0; r < 4; r++) s[j][r] = 0.f;
            #pragma unroll
            for (int ks = 0; ks < 8; ks++) {
                #pragma unroll
                for (int p = 0; p < 4; p++) {
                    uint32_t br[4];
                    LDSM4(br, ksb + (uint32_t)((p * 16 * APAD + ks * 8) * 4));
                    mma_tf32(s[2*p],     qa[qb][ks], &br[0]);
                    mma_tf32(s[2*p + 1], qa[qb][ks], &br[2]);
                }
            }
            float* Pb = Pw + qb * 16 * APAD;
            #pragma unroll
            for (int j = 0; j < 8; j++) {
                float md0 = madd[j * 8 + 2 * gc];
                float md1 = madd[j * 8 + 2 * gc + 1];
                float e0 = __expf(s[j][0] + md0);
                float e1 = __expf(s[j][1] + md1);
                float e2 = __expf(s[j][2] + md0);
                float e3 = __expf(s[j][3] + md1);
                lsum[qb][0] += e0 + e1;
                lsum[qb][1] += e2 + e3;
                float2 p0 = {e0, e1};
                float2 p1 = {e2, e3};
                *(float2*)&Pb[gr * APAD + j * 8 + 2 * gc] = p0;
                *(float2*)&Pb[(gr + 8) * APAD + j * 8 + 2 * gc] = p1;
            }
        }
        __syncwarp();

        // ---- O += P V (VT frag shared across both blocks) ----
        #pragma unroll
        for (int ks = 0; ks < 8; ks++) {
            uint32_t pa0[4], pa1[4];
            LDSM4(pa0, pwb + (uint32_t)((ks * 8) * 4));
            LDSM4(pa1, pwb + (uint32_t)((16 * APAD + ks * 8) * 4));
            #pragma unroll
            for (int p = 0; p < 4; p++) {
                uint32_t br[4];
                LDSM4(br, vtb + (uint32_t)((p * 16 * APAD + ks * 8) * 4));
                mma_tf32(o[0][2*p],     pa0, &br[0]);
                mma_tf32(o[0][2*p + 1], pa0, &br[2]);
                mma_tf32(o[1][2*p],     pa1, &br[0]);
                mma_tf32(o[1][2*p + 1], pa1, &br[2]);
            }
        }
        __syncwarp();
    }

    // ---- single row-sum reduction, normalize + store ----
    #pragma unroll
    for (int qb = 0; qb < 2; qb++)
        #pragma unroll
        for (int off = 1; off <= 2; off <<= 1) {
            lsum[qb][0] += __shfl_xor_sync(0xffffffffu, lsum[qb][0], off);
            lsum[qb][1] += __shfl_xor_sync(0xffffffffu, lsum[qb][1], off);
        }
    float* Ob = O + ((size_t)b * SEQ + q0) * DMODEL + hh * DKH;
    #pragma unroll
    for (int qb = 0; qb < 2; qb++) {
        float inv0 = 1.f / lsum[qb][0], inv1 = 1.f / lsum[qb][1];
        int r0 = wrow + qb * 16 + gr;
        #pragma unroll
        for (int j = 0; j < 8; j++) {
            int col = j * 8 + 2 * gc;
            float2 v0 = {o[qb][j][0] * inv0, o[qb][j][1] * inv0};
            float2 v1 = {o[qb][j][2] * inv1, o[qb][j][3] * inv1};
            *(float2*)&Ob[(size_t)r0 * DMODEL + col] = v0;
            *(float2*)&Ob[(size_t)(r0 + 8) * DMODEL + col] = v1;
        }
    }
}

// ================= launch =================
extern "C" void kernel_launch(void* const* d_in, const int* in_sizes, int n_in,
                              void* d_out, int out_size) {
    const float* x    = (const float*)d_in[0];
    const int*   mask = (const int*)  d_in[1];
    const float* wq = (const float*)d_in[2];  const float* bq = (const float*)d_in[3];
    const float* wk = (const float*)d_in[4];  const float* bk = (const float*)d_in[5];
    const float* wv = (const float*)d_in[6];  const float* bv = (const float*)d_in[7];
    const float* wo = (const float*)d_in[8];  const float* bo = (const float*)d_in[9];
    const float* w1 = (const float*)d_in[10]; const float* b1 = (const float*)d_in[11];
    const float* w2 = (const float*)d_in[12]; const float* b2 = (const float*)d_in[13];
    const float* a1 = (const float*)d_in[14]; const float* g1 = (const float*)d_in[15];
    const float* a2 = (const float*)d_in[16]; const float* g2 = (const float*)d_in[17];
    float* out = (float*)d_out;

    float *h, *qkv, *ctx, *x1, *h2, *ff, *wqkvp, *bqkvp;
    cudaGetSymbolAddress((void**)&h,    g_h);
    cudaGetSymbolAddress((void**)&qkv,  g_qkv);
    cudaGetSymbolAddress((void**)&ctx,  g_ctx);
    cudaGetSymbolAddress((void**)&x1,   g_x1);
    cudaGetSymbolAddress((void**)&h2,   g_h2);
    cudaGetSymbolAddress((void**)&ff,   g_ff);
    cudaGetSymbolAddress((void**)&wqkvp, g_wqkv);
    cudaGetSymbolAddress((void**)&bqkvp, g_bqkv);

    cudaFuncSetAttribute(gemm_mma<0,0>, cudaFuncAttributeMaxDynamicSharedMemorySize, GEMM_SMEM);
    cudaFuncSetAttribute(gemm_mma<0,1>, cudaFuncAttributeMaxDynamicSharedMemorySize, GEMM_SMEM);
    cudaFuncSetAttribute(gemm_mma<1,0>, cudaFuncAttributeMaxDynamicSharedMemorySize, GEMM_SMEM);
    cudaFuncSetAttribute(attn_mma, cudaFuncAttributeMaxDynamicSharedMemorySize, ATTN_SMEM);

    // pack fused qkv weights
    pack_qkv<<<QKVN, 128>>>(wq, wk, wv, bq, bk, bv);

    // LN1 (warp per row)
    ln_k<<<MROWS / 4, 128>>>(x, h, a1, g1);

    // fused QKV projection
    dim3 gqkv(QKVN / 128, MROWS / 128);
    gemm_mma<0,0><<<gqkv, 256, GEMM_SMEM>>>(h, wqkvp, bqkvp, nullptr, qkv, MROWS, QKVN, DMODEL);

    // attention
    dim3 ga(NB * NH, SEQ / 128);
    attn_mma<<<ga, 128, ATTN_SMEM>>>(qkv, mask, ctx);

    // output projection + residual
    dim3 gp(DMODEL / 128, MROWS / 128);
    gemm_mma<0,1><<<gp, 256, GEMM_SMEM>>>(ctx, wo, bo, x, x1, MROWS, DMODEL, DMODEL);

    // LN2
    ln_k<<<MROWS / 4, 128>>>(x1, h2, a2, g2);

    // FFN
    dim3 gf1(FDIM / 128, MROWS / 128);
    gemm_mma<1,0><<<gf1, 256, GEMM_SMEM>>>(h2, w1, b1, nullptr, ff, MROWS, FDIM, DMODEL);
    gemm_mma<0,1><<<gp, 256, GEMM_SMEM>>>(ff, w2, b2, x1, out, MROWS, DMODEL, FDIM);
}

// round 16
// speedup vs baseline: 1.1208x; 1.1208x over previous
#include <cuda_runtime.h>
#include <math.h>
#include <stdint.h>

#define NB     4
#define SEQ    2048
#define DMODEL 512
#define NH     8
#define DKH    64
#define FDIM   2048
#define MROWS  (NB*SEQ)   // 8192
#define QKVN   1536

// -------- scratch (device globals; no allocation allowed) --------
__device__ float g_h   [MROWS*DMODEL];
__device__ float g_qkv [MROWS*QKVN];
__device__ float g_ctx [MROWS*DMODEL];
__device__ float g_x1  [MROWS*DMODEL];
__device__ float g_h2  [MROWS*DMODEL];
__device__ float g_ff  [MROWS*FDIM];

// ================= helpers =================
__device__ __forceinline__ uint32_t smem_u32(const void* p) {
    uint32_t a;
    asm("{ .reg .u64 t; cvta.to.shared.u64 t, %1; cvt.u32.u64 %0, t; }" : "=r"(a) : "l"(p));
    return a;
}
__device__ __forceinline__ void cp16(uint32_t dst, const void* src) {
    asm volatile("cp.async.cg.shared.global [%0], [%1], 16;" :: "r"(dst), "l"(src) : "memory");
}
__device__ __forceinline__ uint32_t f2r(float f) { return __float_as_uint(f); }
__device__ __forceinline__ void mma_tf32(float* c, const uint32_t* a, const uint32_t* b) {
    asm volatile("mma.sync.aligned.m16n8k8.row.col.f32.tf32.tf32.f32 "
        "{%0,%1,%2,%3}, {%4,%5,%6,%7}, {%8,%9}, {%0,%1,%2,%3};"
        : "+f"(c[0]), "+f"(c[1]), "+f"(c[2]), "+f"(c[3])
        : "r"(a[0]), "r"(a[1]), "r"(a[2]), "r"(a[3]), "r"(b[0]), "r"(b[1]));
}
#define LDSM4(R, addr) asm volatile( \
    "ldmatrix.sync.aligned.m8n8.x4.shared.b16 {%0,%1,%2,%3}, [%4];" \
    : "=r"((R)[0]), "=r"((R)[1]), "=r"((R)[2]), "=r"((R)[3]) : "r"(addr))
#define CP_COMMIT()  asm volatile("cp.async.commit_group;" ::: "memory")
#define CP_WAIT0()   asm volatile("cp.async.wait_group 0;" ::: "memory")

// ================= LayerNorm (torch semantics), warp-per-row =================
__global__ __launch_bounds__(128) void ln_k(const float* __restrict__ x,
                                            float* __restrict__ out,
                                            const float* __restrict__ alpha,
                                            const float* __restrict__ beta) {
    int row = blockIdx.x * 4 + (threadIdx.x >> 5);
    int lane = threadIdx.x & 31;
    const float4* xr = (const float4*)(x + (size_t)row * DMODEL);
    float4 v[4];
    #pragma unroll
    for (int i = 0; i < 4; i++) v[i] = xr[lane + 32 * i];
    float s = 0.f;
    #pragma unroll
    for (int i = 0; i < 4; i++) s += v[i].x + v[i].y + v[i].z + v[i].w;
    #pragma unroll
    for (int o = 16; o; o >>= 1) s += __shfl_xor_sync(0xffffffffu, s, o);
    float mean = s * (1.f / DMODEL);
    float ss = 0.f;
    #pragma unroll
    for (int i = 0; i < 4; i++) {
        v[i].x -= mean; v[i].y -= mean; v[i].z -= mean; v[i].w -= mean;
        ss += v[i].x * v[i].x + v[i].y * v[i].y + v[i].z * v[i].z + v[i].w * v[i].w;
    }
    #pragma unroll
    for (int o = 16; o; o >>= 1) ss += __shfl_xor_sync(0xffffffffu, ss, o);
    float var = ss * (1.f / (DMODEL - 1));
    float inv = 1.f / (sqrtf(var) + 1e-6f);
    float a = alpha[0], b = beta[0];
    float4* orow = (float4*)(out + (size_t)row * DMODEL);
    #pragma unroll
    for (int i = 0; i < 4; i++) {
        float4 o4;
        o4.x = a * v[i].x * inv + b;
        o4.y = a * v[i].y * inv + b;
        o4.z = a * v[i].z * inv + b;
        o4.w = a * v[i].w * inv + b;
        orow[lane + 32 * i] = o4;
    }
}

// ================= tf32 warp-MMA GEMM 128x128 (proven, 2-stage) =================
#define GROW 36
#define ATILE_B (128 * GROW * 4)
#define STAGE_B (2 * ATILE_B)
#define GEMM_SMEM (2 * STAGE_B)

template<int RELU, int RES>
__device__ __forceinline__ void gemm_core(const float* __restrict__ Abase,
                                          const float* __restrict__ Bbase,
                                          const float* __restrict__ bias,  // tile-local (bn offset applied)
                                          const float* __restrict__ res,
                                          float* __restrict__ C,
                                          int bm, int bn, int N, int K, char* smem) {
    uint32_t sb = smem_u32(smem);
    int tid = threadIdx.x, wid = tid >> 5, lane = tid & 31;
    int gr = lane >> 2, gc = lane & 3;
    int g = lane >> 3;
    int wm = (wid >> 2) * 64, wn = (wid & 3) * 32;

    uint32_t a_lane = (uint32_t)((wm + (g & 1) * 8 + (lane & 7)) * GROW + (g >> 1) * 4);
    uint32_t b_lane = (uint32_t)((wn + (lane & 7) + ((lane >> 4) & 1) * 8) * GROW + ((lane >> 3) & 1) * 4);

    float acc[4][4][4];
    #pragma unroll
    for (int i = 0; i < 4; i++)
        #pragma unroll
        for (int j = 0; j < 4; j++)
            #pragma unroll
            for (int r = 0; r < 4; r++) acc[i][j][r] = 0.f;

    int lrow = tid >> 3, lc4 = tid & 7;

    auto load_chunk = [&](int c, int s) {
        uint32_t ab = sb + s * STAGE_B;
        uint32_t bb = ab + ATILE_B;
        const float* Ap = Abase + c * 32;
        const float* Bp = Bbase + c * 32;
        #pragma unroll
        for (int i = 0; i < 4; i++) {
            int row = i * 32 + lrow;
            uint32_t off = (uint32_t)(row * (GROW * 4) + lc4 * 16);
            cp16(ab + off, Ap + (size_t)row * K + lc4 * 4);
            cp16(bb + off, Bp + (size_t)row * K + lc4 * 4);
        }
    };

    const int NC = K / 32;
    load_chunk(0, 0);
    CP_COMMIT();
    CP_WAIT0();
    __syncthreads();

    int buf = 0;
    for (int ch = 0; ch < NC; ch++) {
        if (ch + 1 < NC) {
            load_chunk(ch + 1, buf ^ 1);
            CP_COMMIT();
        }
        uint32_t ab = sb + buf * STAGE_B + a_lane * 4;
        uint32_t bb = sb + buf * STAGE_B + ATILE_B + b_lane * 4;
        #pragma unroll
        for (int ks = 0; ks < 4; ks++) {
            uint32_t ar[4][4];
            #pragma unroll
            for (int i = 0; i < 4; i++)
                LDSM4(ar[i], ab + (uint32_t)((i * 16 * GROW + ks * 8) * 4));
            uint32_t br[2][4];
            #pragma unroll
            for (int p = 0; p < 2; p++)
                LDSM4(br[p], bb + (uint32_t)((p * 16 * GROW + ks * 8) * 4));
            #pragma unroll
            for (int i = 0; i < 4; i++)
                #pragma unroll
                for (int j = 0; j < 4; j++)
                    mma_tf32(acc[i][j], ar[i], &br[j >> 1][(j & 1) * 2]);
        }
        if (ch + 1 < NC)
            CP_WAIT0();
        __syncthreads();
        buf ^= 1;
    }

    #pragma unroll
    for (int i = 0; i < 4; i++) {
        int row0 = bm + wm + i * 16 + gr;
        #pragma unroll
        for (int j = 0; j < 4; j++) {
            int lcol = wn + j * 8 + 2 * gc;     // 0..127 within tile
            int col = bn + lcol;
            float2 b2 = *(const float2*)&bias[lcol];
            float2 v0, v1;
            v0.x = acc[i][j][0] + b2.x; v0.y = acc[i][j][1] + b2.y;
            v1.x = acc[i][j][2] + b2.x; v1.y = acc[i][j][3] + b2.y;
            if (RELU) {
                v0.x = fmaxf(v0.x, 0.f); v0.y = fmaxf(v0.y, 0.f);
                v1.x = fmaxf(v1.x, 0.f); v1.y = fmaxf(v1.y, 0.f);
            }
            if (RES) {
                float2 r0 = *(const float2*)&res[(size_t)row0 * N + col];
                float2 r1 = *(const float2*)&res[(size_t)(row0 + 8) * N + col];
                v0.x += r0.x; v0.y += r0.y;
                v1.x += r1.x; v1.y += r1.y;
            }
            *(float2*)&C[(size_t)row0 * N + col] = v0;
            *(float2*)&C[(size_t)(row0 + 8) * N + col] = v1;
        }
    }
}

template<int RELU, int RES>
__global__ __launch_bounds__(256) void gemm_mma(const float* __restrict__ A,
                                                const float* __restrict__ B,
                                                const float* __restrict__ bias,
                                                const float* __restrict__ res,
                                                float* __restrict__ C,
                                                int M, int N, int K) {
    extern __shared__ char smem[];
    int bm = blockIdx.y * 128, bn = blockIdx.x * 128;
    gemm_core<RELU, RES>(A + (size_t)bm * K, B + (size_t)bn * K, bias + bn,
                         res, C, bm, bn, N, K, smem);
}

// Fused QKV GEMM: N-tile index selects wq/wk/wv directly (no packing).
// Output row stride QKVN; q at cols 0-511, k at 512-1023, v at 1024-1535.
__global__ __launch_bounds__(256) void qkv_gemm(const float* __restrict__ A,
                                                const float* __restrict__ wq,
                                                const float* __restrict__ wk,
                                                const float* __restrict__ wv,
                                                const float* __restrict__ bq,
                                                const float* __restrict__ bk,
                                                const float* __restrict__ bv,
                                                float* __restrict__ C) {
    extern __shared__ char smem[];
    int bm = blockIdx.y * 128, bn = blockIdx.x * 128;
    int sel = blockIdx.x >> 2;            // 0..3 tiles per 512-wide weight
    int wrow = (blockIdx.x & 3) * 128;    // row offset within the selected weight
    const float* W  = (sel == 0) ? wq : (sel == 1) ? wk : wv;
    const float* Bi = (sel == 0) ? bq : (sel == 1) ? bk : bv;
    gemm_core<0, 0>(A + (size_t)bm * DMODEL, W + (size_t)wrow * DMODEL, Bi + wrow,
                    nullptr, C, bm, bn, QKVN, DMODEL, smem);
}

// ================= tf32 warp-MMA flash attention: 4 warps x 32 queries (r14 proven) =================
#define APAD 68
#define AT_KS   0
#define AT_VT   (64 * APAD)
#define AT_MADD (2 * 64 * APAD)
#define AT_PS   (2 * 64 * APAD + 64)
#define ATTN_SMEM ((2 * 64 * APAD + 64 + 4 * 32 * APAD) * 4)

__global__ __launch_bounds__(128, 2) void attn_mma(const float* __restrict__ QKV,
                                                   const int* __restrict__ mask,
                                                   float* __restrict__ O) {
    extern __shared__ float sm[];
    uint32_t sb = smem_u32(sm);
    float* VT   = sm + AT_VT;
    float* madd = sm + AT_MADD;

    int tid = threadIdx.x, wid = tid >> 5, lane = tid & 31;
    int gr = lane >> 2, gc = lane & 3;
    int g = lane >> 3;
    int bh = blockIdx.x, b = bh >> 3, hh = bh & 7;
    int q0 = blockIdx.y * 128;
    int wrow = wid * 32;

    const int LD = QKVN;
    const float* Qb = QKV + ((size_t)b * SEQ + q0) * LD + hh * DKH;
    const float* Kb = QKV + (size_t)b * SEQ * LD + 512 + hh * DKH;
    const float* Vb = QKV + (size_t)b * SEQ * LD + 1024 + hh * DKH;
    float* Pw = sm + AT_PS + wid * 32 * APAD;

    uint32_t bk_lane = (uint32_t)(((lane & 7) + ((lane >> 4) & 1) * 8) * APAD + ((lane >> 3) & 1) * 4);
    uint32_t pa_lane = (uint32_t)(((g & 1) * 8 + (lane & 7)) * APAD + (g >> 1) * 4);
    uint32_t ksb = sb + AT_KS * 4 + bk_lane * 4;
    uint32_t vtb = sb + AT_VT * 4 + bk_lane * 4;
    uint32_t pwb = sb + (AT_PS + wid * 32 * APAD) * 4 + pa_lane * 4;

    // Q fragments for 2 query blocks of 16 rows (pre-scaled by 1/8)
    uint32_t qa[2][8][4];
    #pragma unroll
    for (int qb = 0; qb < 2; qb++)
        #pragma unroll
        for (int ks = 0; ks < 8; ks++) {
            int r0 = wrow + qb * 16 + gr, c0 = ks * 8 + gc;
            qa[qb][ks][0] = f2r(Qb[(size_t)r0 * LD + c0] * 0.125f);
            qa[qb][ks][1] = f2r(Qb[(size_t)(r0 + 8) * LD + c0] * 0.125f);
            qa[qb][ks][2] = f2r(Qb[(size_t)r0 * LD + c0 + 4] * 0.125f);
            qa[qb][ks][3] = f2r(Qb[(size_t)(r0 + 8) * LD + c0 + 4] * 0.125f);
        }

    float o[2][8][4];
    #pragma unroll
    for (int qb = 0; qb < 2; qb++)
        #pragma unroll
        for (int j = 0; j < 8; j++)
            #pragma unroll
            for (int r = 0; r < 4; r++) o[qb][j][r] = 0.f;
    float lsum[2][2] = {{0.f, 0.f}, {0.f, 0.f}};

    int vd = tid & 63, vk4 = (tid >> 6) * 32;
    for (int kt = 0; kt < SEQ; kt += 64) {
        __syncthreads();
        // K tile -> Ks[key][dim]
        #pragma unroll
        for (int i = 0; i < 8; i++) {
            int li = i * 128 + tid;
            int row = li >> 4, c16 = li & 15;
            cp16(sb + (uint32_t)((AT_KS + row * APAD + c16 * 4) * 4),
                 Kb + (size_t)(kt + row) * LD + c16 * 4);
        }
        CP_COMMIT();
        // V tile transposed -> VT[dim][key]
        #pragma unroll
        for (int i = 0; i < 32; i++) {
            VT[vd * APAD + vk4 + i] = __ldg(&Vb[(size_t)(kt + vk4 + i) * LD + vd]);
        }
        if (tid < 64)
            madd[tid] = (mask[b * SEQ + kt + tid] == 0) ? -1e9f : 0.f;
        CP_WAIT0();
        __syncthreads();

        // ---- S = Q K^T for both query blocks (K frag shared) ----
        float s[2][8][4];
        #pragma unroll
        for (int qb = 0; qb < 2; qb++)
            #pragma unroll
            for (int j = 0; j < 8; j++)
                #pragma unroll
                for (int r = 0; r < 4; r++) s[qb][j][r] = 0.f;
        #pragma unroll
        for (int ks = 0; ks < 8; ks++) {
            #pragma unroll
            for (int p = 0; p < 4; p++) {
                uint32_t br[4];
                LDSM4(br, ksb + (uint32_t)((p * 16 * APAD + ks * 8) * 4));
                mma_tf32(s[0][2*p],     qa[0][ks], &br[0]);
                mma_tf32(s[0][2*p + 1], qa[0][ks], &br[2]);
                mma_tf32(s[1][2*p],     qa[1][ks], &br[0]);
                mma_tf32(s[1][2*p + 1], qa[1][ks], &br[2]);
            }
        }

        // ---- mask + exp (no max subtraction) + P to smem ----
        #pragma unroll
        for (int qb = 0; qb < 2; qb++) {
            float* Pb = Pw + qb * 16 * APAD;
            #pragma unroll
            for (int j = 0; j < 8; j++) {
                float md0 = madd[j * 8 + 2 * gc];
                float md1 = madd[j * 8 + 2 * gc + 1];
                float e0 = __expf(s[qb][j][0] + md0);
                float e1 = __expf(s[qb][j][1] + md1);
                float e2 = __expf(s[qb][j][2] + md0);
                float e3 = __expf(s[qb][j][3] + md1);
                lsum[qb][0] += e0 + e1;
                lsum[qb][1] += e2 + e3;
                float2 p0 = {e0, e1};
                float2 p1 = {e2, e3};
                *(float2*)&Pb[gr * APAD + j * 8 + 2 * gc] = p0;
                *(float2*)&Pb[(gr + 8) * APAD + j * 8 + 2 * gc] = p1;
            }
        }
        __syncwarp();

        // ---- O += P V ----
        #pragma unroll
        for (int ks = 0; ks < 8; ks++) {
            uint32_t pa0[4], pa1[4];
            LDSM4(pa0, pwb + (uint32_t)((ks * 8) * 4));
            LDSM4(pa1, pwb + (uint32_t)((16 * APAD + ks * 8) * 4));
            #pragma unroll
            for (int p = 0; p < 4; p++) {
                uint32_t br[4];
                LDSM4(br, vtb + (uint32_t)((p * 16 * APAD + ks * 8) * 4));
                mma_tf32(o[0][2*p],     pa0, &br[0]);
                mma_tf32(o[0][2*p + 1], pa0, &br[2]);
                mma_tf32(o[1][2*p],     pa1, &br[0]);
                mma_tf32(o[1][2*p + 1], pa1, &br[2]);
            }
        }
        __syncwarp();
    }

    // ---- single row-sum reduction, normalize + store ----
    #pragma unroll
    for (int qb = 0; qb < 2; qb++)
        #pragma unroll
        for (int off = 1; off <= 2; off <<= 1) {
            lsum[qb][0] += __shfl_xor_sync(0xffffffffu, lsum[qb][0], off);
            lsum[qb][1] += __shfl_xor_sync(0xffffffffu, lsum[qb][1], off);
        }
    float* Ob = O + ((size_t)b * SEQ + q0) * DMODEL + hh * DKH;
    #pragma unroll
    for (int qb = 0; qb < 2; qb++) {
        float inv0 = 1.f / lsum[qb][0], inv1 = 1.f / lsum[qb][1];
        int r0 = wrow + qb * 16 + gr;
        #pragma unroll
        for (int j = 0; j < 8; j++) {
            int col = j * 8 + 2 * gc;
            float2 v0 = {o[qb][j][0] * inv0, o[qb][j][1] * inv0};
            float2 v1 = {o[qb][j][2] * inv1, o[qb][j][3] * inv1};
            *(float2*)&Ob[(size_t)r0 * DMODEL + col] = v0;
            *(float2*)&Ob[(size_t)(r0 + 8) * DMODEL + col] = v1;
        }
    }
}

// ================= launch =================
extern "C" void kernel_launch(void* const* d_in, const int* in_sizes, int n_in,
                              void* d_out, int out_size) {
    const float* x    = (const float*)d_in[0];
    const int*   mask = (const int*)  d_in[1];
    const float* wq = (const float*)d_in[2];  const float* bq = (const float*)d_in[3];
    const float* wk = (const float*)d_in[4];  const float* bk = (const float*)d_in[5];
    const float* wv = (const float*)d_in[6];  const float* bv = (const float*)d_in[7];
    const float* wo = (const float*)d_in[8];  const float* bo = (const float*)d_in[9];
    const float* w1 = (const float*)d_in[10]; const float* b1 = (const float*)d_in[11];
    const float* w2 = (const float*)d_in[12]; const float* b2 = (const float*)d_in[13];
    const float* a1 = (const float*)d_in[14]; const float* g1 = (const float*)d_in[15];
    const float* a2 = (const float*)d_in[16]; const float* g2 = (const float*)d_in[17];
    float* out = (float*)d_out;

    float *h, *qkv, *ctx, *x1, *h2, *ff;
    cudaGetSymbolAddress((void**)&h,    g_h);
    cudaGetSymbolAddress((void**)&qkv,  g_qkv);
    cudaGetSymbolAddress((void**)&ctx,  g_ctx);
    cudaGetSymbolAddress((void**)&x1,   g_x1);
    cudaGetSymbolAddress((void**)&h2,   g_h2);
    cudaGetSymbolAddress((void**)&ff,   g_ff);

    cudaFuncSetAttribute(qkv_gemm,      cudaFuncAttributeMaxDynamicSharedMemorySize, GEMM_SMEM);
    cudaFuncSetAttribute(gemm_mma<0,1>, cudaFuncAttributeMaxDynamicSharedMemorySize, GEMM_SMEM);
    cudaFuncSetAttribute(gemm_mma<1,0>, cudaFuncAttributeMaxDynamicSharedMemorySize, GEMM_SMEM);
    cudaFuncSetAttribute(attn_mma, cudaFuncAttributeMaxDynamicSharedMemorySize, ATTN_SMEM);

    // LN1 (warp per row)
    ln_k<<<MROWS / 4, 128>>>(x, h, a1, g1);

    // fused QKV projection (direct-indexed weights, no pack kernel)
    dim3 gqkv(QKVN / 128, MROWS / 128);
    qkv_gemm<<<gqkv, 256, GEMM_SMEM>>>(h, wq, wk, wv, bq, bk, bv, qkv);

    // attention
    dim3 ga(NB * NH, SEQ / 128);
    attn_mma<<<ga, 128, ATTN_SMEM>>>(qkv, mask, ctx);

    // output projection + residual
    dim3 gp(DMODEL / 128, MROWS / 128);
    gemm_mma<0,1><<<gp, 256, GEMM_SMEM>>>(ctx, wo, bo, x, x1, MROWS, DMODEL, DMODEL);

    // LN2
    ln_k<<<MROWS / 4, 128>>>(x1, h2, a2, g2);

    // FFN
    dim3 gf1(FDIM / 128, MROWS / 128);
    gemm_mma<1,0><<<gf1, 256, GEMM_SMEM>>>(h2, w1, b1, nullptr, ff, MROWS, FDIM, DMODEL);
    gemm_mma<0,1><<<gp, 256, GEMM_SMEM>>>(ff, w2, b2, x1, out, MROWS, DMODEL, FDIM);
}

// round 17
// speedup vs baseline: 1.2704x; 1.1334x over previous
#include <cuda_runtime.h>
#include <cuda_fp16.h>
#include <math.h>
#include <stdint.h>

#define NB     4
#define SEQ    2048
#define DMODEL 512
#define NH     8
#define DKH    64
#define FDIM   2048
#define MROWS  (NB*SEQ)   // 8192
#define QKVN   1536

// -------- scratch (device globals; no allocation allowed) --------
__device__ float  g_h   [MROWS*DMODEL];
__device__ __half g_qkvh[MROWS*QKVN];     // fp16 fused qkv (q pre-scaled by 1/8)
__device__ float  g_ctx [MROWS*DMODEL];
__device__ float  g_x1  [MROWS*DMODEL];
__device__ float  g_h2  [MROWS*DMODEL];
__device__ float  g_ff  [MROWS*FDIM];

// ================= helpers =================
__device__ __forceinline__ uint32_t smem_u32(const void* p) {
    uint32_t a;
    asm("{ .reg .u64 t; cvta.to.shared.u64 t, %1; cvt.u32.u64 %0, t; }" : "=r"(a) : "l"(p));
    return a;
}
__device__ __forceinline__ void cp16(uint32_t dst, const void* src) {
    asm volatile("cp.async.cg.shared.global [%0], [%1], 16;" :: "r"(dst), "l"(src) : "memory");
}
__device__ __forceinline__ uint32_t f2r(float f) { return __float_as_uint(f); }
__device__ __forceinline__ void mma_tf32(float* c, const uint32_t* a, const uint32_t* b) {
    asm volatile("mma.sync.aligned.m16n8k8.row.col.f32.tf32.tf32.f32 "
        "{%0,%1,%2,%3}, {%4,%5,%6,%7}, {%8,%9}, {%0,%1,%2,%3};"
        : "+f"(c[0]), "+f"(c[1]), "+f"(c[2]), "+f"(c[3])
        : "r"(a[0]), "r"(a[1]), "r"(a[2]), "r"(a[3]), "r"(b[0]), "r"(b[1]));
}
__device__ __forceinline__ void mma_f16(float* c, const uint32_t* a, const uint32_t* b) {
    asm volatile("mma.sync.aligned.m16n8k16.row.col.f32.f16.f16.f32 "
        "{%0,%1,%2,%3}, {%4,%5,%6,%7}, {%8,%9}, {%0,%1,%2,%3};"
        : "+f"(c[0]), "+f"(c[1]), "+f"(c[2]), "+f"(c[3])
        : "r"(a[0]), "r"(a[1]), "r"(a[2]), "r"(a[3]), "r"(b[0]), "r"(b[1]));
}
#define LDSM4(R, addr) asm volatile( \
    "ldmatrix.sync.aligned.m8n8.x4.shared.b16 {%0,%1,%2,%3}, [%4];" \
    : "=r"((R)[0]), "=r"((R)[1]), "=r"((R)[2]), "=r"((R)[3]) : "r"(addr))
#define LDSM4T(R, addr) asm volatile( \
    "ldmatrix.sync.aligned.m8n8.x4.trans.shared.b16 {%0,%1,%2,%3}, [%4];" \
    : "=r"((R)[0]), "=r"((R)[1]), "=r"((R)[2]), "=r"((R)[3]) : "r"(addr))
#define CP_COMMIT()  asm volatile("cp.async.commit_group;" ::: "memory")
#define CP_WAIT0()   asm volatile("cp.async.wait_group 0;" ::: "memory")

// ================= LayerNorm (torch semantics), warp-per-row =================
__global__ __launch_bounds__(128) void ln_k(const float* __restrict__ x,
                                            float* __restrict__ out,
                                            const float* __restrict__ alpha,
                                            const float* __restrict__ beta) {
    int row = blockIdx.x * 4 + (threadIdx.x >> 5);
    int lane = threadIdx.x & 31;
    const float4* xr = (const float4*)(x + (size_t)row * DMODEL);
    float4 v[4];
    #pragma unroll
    for (int i = 0; i < 4; i++) v[i] = xr[lane + 32 * i];
    float s = 0.f;
    #pragma unroll
    for (int i = 0; i < 4; i++) s += v[i].x + v[i].y + v[i].z + v[i].w;
    #pragma unroll
    for (int o = 16; o; o >>= 1) s += __shfl_xor_sync(0xffffffffu, s, o);
    float mean = s * (1.f / DMODEL);
    float ss = 0.f;
    #pragma unroll
    for (int i = 0; i < 4; i++) {
        v[i].x -= mean; v[i].y -= mean; v[i].z -= mean; v[i].w -= mean;
        ss += v[i].x * v[i].x + v[i].y * v[i].y + v[i].z * v[i].z + v[i].w * v[i].w;
    }
    #pragma unroll
    for (int o = 16; o; o >>= 1) ss += __shfl_xor_sync(0xffffffffu, ss, o);
    float var = ss * (1.f / (DMODEL - 1));
    float inv = 1.f / (sqrtf(var) + 1e-6f);
    float a = alpha[0], b = beta[0];
    float4* orow = (float4*)(out + (size_t)row * DMODEL);
    #pragma unroll
    for (int i = 0; i < 4; i++) {
        float4 o4;
        o4.x = a * v[i].x * inv + b;
        o4.y = a * v[i].y * inv + b;
        o4.z = a * v[i].z * inv + b;
        o4.w = a * v[i].w * inv + b;
        orow[lane + 32 * i] = o4;
    }
}

// ================= tf32 warp-MMA GEMM 128x128 (proven, 2-stage) =================
#define GROW 36
#define ATILE_B (128 * GROW * 4)
#define STAGE_B (2 * ATILE_B)
#define GEMM_SMEM (2 * STAGE_B)

// H16=0: fp32 C output. H16=1: fp16 C output (row stride N halves), scaled.
template<int RELU, int RES, int H16>
__device__ __forceinline__ void gemm_core(const float* __restrict__ Abase,
                                          const float* __restrict__ Bbase,
                                          const float* __restrict__ bias,  // tile-local
                                          const float* __restrict__ res,
                                          void* __restrict__ Cout,
                                          float oscale,
                                          int bm, int bn, int N, int K, char* smem) {
    uint32_t sb = smem_u32(smem);
    int tid = threadIdx.x, wid = tid >> 5, lane = tid & 31;
    int gr = lane >> 2, gc = lane & 3;
    int g = lane >> 3;
    int wm = (wid >> 2) * 64, wn = (wid & 3) * 32;

    uint32_t a_lane = (uint32_t)((wm + (g & 1) * 8 + (lane & 7)) * GROW + (g >> 1) * 4);
    uint32_t b_lane = (uint32_t)((wn + (lane & 7) + ((lane >> 4) & 1) * 8) * GROW + ((lane >> 3) & 1) * 4);

    float acc[4][4][4];
    #pragma unroll
    for (int i = 0; i < 4; i++)
        #pragma unroll
        for (int j = 0; j < 4; j++)
            #pragma unroll
            for (int r = 0; r < 4; r++) acc[i][j][r] = 0.f;

    int lrow = tid >> 3, lc4 = tid & 7;

    auto load_chunk = [&](int c, int s) {
        uint32_t ab = sb + s * STAGE_B;
        uint32_t bb = ab + ATILE_B;
        const float* Ap = Abase + c * 32;
        const float* Bp = Bbase + c * 32;
        #pragma unroll
        for (int i = 0; i < 4; i++) {
            int row = i * 32 + lrow;
            uint32_t off = (uint32_t)(row * (GROW * 4) + lc4 * 16);
            cp16(ab + off, Ap + (size_t)row * K + lc4 * 4);
            cp16(bb + off, Bp + (size_t)row * K + lc4 * 4);
        }
    };

    const int NC = K / 32;
    load_chunk(0, 0);
    CP_COMMIT();
    CP_WAIT0();
    __syncthreads();

    int buf = 0;
    for (int ch = 0; ch < NC; ch++) {
        if (ch + 1 < NC) {
            load_chunk(ch + 1, buf ^ 1);
            CP_COMMIT();
        }
        uint32_t ab = sb + buf * STAGE_B + a_lane * 4;
        uint32_t bb = sb + buf * STAGE_B + ATILE_B + b_lane * 4;
        #pragma unroll
        for (int ks = 0; ks < 4; ks++) {
            uint32_t ar[4][4];
            #pragma unroll
            for (int i = 0; i < 4; i++)
                LDSM4(ar[i], ab + (uint32_t)((i * 16 * GROW + ks * 8) * 4));
            uint32_t br[2][4];
            #pragma unroll
            for (int p = 0; p < 2; p++)
                LDSM4(br[p], bb + (uint32_t)((p * 16 * GROW + ks * 8) * 4));
            #pragma unroll
            for (int i = 0; i < 4; i++)
                #pragma unroll
                for (int j = 0; j < 4; j++)
                    mma_tf32(acc[i][j], ar[i], &br[j >> 1][(j & 1) * 2]);
        }
        if (ch + 1 < NC)
            CP_WAIT0();
        __syncthreads();
        buf ^= 1;
    }

    #pragma unroll
    for (int i = 0; i < 4; i++) {
        int row0 = bm + wm + i * 16 + gr;
        #pragma unroll
        for (int j = 0; j < 4; j++) {
            int lcol = wn + j * 8 + 2 * gc;
            int col = bn + lcol;
            float2 b2 = *(const float2*)&bias[lcol];
            float2 v0, v1;
            v0.x = acc[i][j][0] + b2.x; v0.y = acc[i][j][1] + b2.y;
            v1.x = acc[i][j][2] + b2.x; v1.y = acc[i][j][3] + b2.y;
            if (RELU) {
                v0.x = fmaxf(v0.x, 0.f); v0.y = fmaxf(v0.y, 0.f);
                v1.x = fmaxf(v1.x, 0.f); v1.y = fmaxf(v1.y, 0.f);
            }
            if (RES) {
                const float* resp = (const float*)res;
                float2 r0 = *(const float2*)&resp[(size_t)row0 * N + col];
                float2 r1 = *(const float2*)&resp[(size_t)(row0 + 8) * N + col];
                v0.x += r0.x; v0.y += r0.y;
                v1.x += r1.x; v1.y += r1.y;
            }
            if (H16) {
                __half2* C16 = (__half2*)Cout;
                C16[((size_t)row0 * N + col) >> 1] = __floats2half2_rn(v0.x * oscale, v0.y * oscale);
                C16[((size_t)(row0 + 8) * N + col) >> 1] = __floats2half2_rn(v1.x * oscale, v1.y * oscale);
            } else {
                float* C = (float*)Cout;
                *(float2*)&C[(size_t)row0 * N + col] = v0;
                *(float2*)&C[(size_t)(row0 + 8) * N + col] = v1;
            }
        }
    }
}

template<int RELU, int RES>
__global__ __launch_bounds__(256) void gemm_mma(const float* __restrict__ A,
                                                const float* __restrict__ B,
                                                const float* __restrict__ bias,
                                                const float* __restrict__ res,
                                                float* __restrict__ C,
                                                int M, int N, int K) {
    extern __shared__ char smem[];
    int bm = blockIdx.y * 128, bn = blockIdx.x * 128;
    gemm_core<RELU, RES, 0>(A + (size_t)bm * K, B + (size_t)bn * K, bias + bn,
                            res, C, 1.f, bm, bn, N, K, smem);
}

// Fused QKV GEMM -> fp16 output. Q columns (sel==0) pre-scaled by 1/8.
__global__ __launch_bounds__(256) void qkv_gemm(const float* __restrict__ A,
                                                const float* __restrict__ wq,
                                                const float* __restrict__ wk,
                                                const float* __restrict__ wv,
                                                const float* __restrict__ bq,
                                                const float* __restrict__ bk,
                                                const float* __restrict__ bv,
                                                __half* __restrict__ C) {
    extern __shared__ char smem[];
    int bm = blockIdx.y * 128, bn = blockIdx.x * 128;
    int sel = blockIdx.x >> 2;
    int wrow = (blockIdx.x & 3) * 128;
    const float* W  = (sel == 0) ? wq : (sel == 1) ? wk : wv;
    const float* Bi = (sel == 0) ? bq : (sel == 1) ? bk : bv;
    float oscale = (sel == 0) ? 0.125f : 1.0f;
    gemm_core<0, 0, 1>(A + (size_t)bm * DMODEL, W + (size_t)wrow * DMODEL, Bi + wrow,
                       nullptr, C, oscale, bm, bn, QKVN, DMODEL, smem);
}

// ================= fp16 m16n8k16 flash attention: 4 warps x 32 queries =================
// smem (halves): Ks[64][72], Vs[64][72] (both [key][dim]), P[128][72] (per-warp 32 rows,
// doubles as Q staging), madd floats at tail.
#define HPAD 72
#define HKS  0
#define HVS  (64 * HPAD)
#define HP   (2 * 64 * HPAD)
#define MADD_B ((2 * 64 * HPAD + 128 * HPAD) * 2)
#define ATTN_SMEM (MADD_B + 64 * 4)

__global__ __launch_bounds__(128, 2) void attn_mma(const __half* __restrict__ QKV,
                                                   const int* __restrict__ mask,
                                                   float* __restrict__ O) {
    extern __shared__ __half smh[];
    uint32_t sb = smem_u32(smh);
    float* madd = (float*)((char*)smh + MADD_B);

    int tid = threadIdx.x, wid = tid >> 5, lane = tid & 31;
    int gr = lane >> 2, gc = lane & 3;
    int bh = blockIdx.x, b = bh >> 3, hh = bh & 7;
    int q0 = blockIdx.y * 128;
    int wrow = wid * 32;

    const int LD = QKVN;
    const __half* Qb = QKV + ((size_t)b * SEQ + q0 + wrow) * LD + hh * DKH;  // warp's 32 rows
    const __half* Kb = QKV + (size_t)b * SEQ * LD + 512 + hh * DKH;
    const __half* Vb = QKV + (size_t)b * SEQ * LD + 1024 + hh * DKH;

    uint32_t pw_half = (uint32_t)(HP + wid * 32 * HPAD);   // warp's P region (halves)

    // ---- stage this warp's Q rows into its P region, build A fragments ----
    #pragma unroll
    for (int i = 0; i < 8; i++) {
        int li = i * 32 + lane;
        int row = li >> 3, c8 = li & 7;
        cp16(sb + (uint32_t)((pw_half + row * HPAD + c8 * 8) * 2),
             Qb + (size_t)row * LD + c8 * 8);
    }
    CP_COMMIT();
    CP_WAIT0();
    __syncwarp();

    // A-frag ldmatrix lane address (within a 16-row block, chunk kc)
    uint32_t aoff = (uint32_t)(((lane & 7) + 8 * ((lane >> 3) & 1)) * HPAD + 8 * (lane >> 4));
    uint32_t qa[2][4][4];
    #pragma unroll
    for (int qb = 0; qb < 2; qb++)
        #pragma unroll
        for (int kc = 0; kc < 4; kc++)
            LDSM4(qa[qb][kc], sb + (uint32_t)((pw_half + qb * 16 * HPAD + kc * 16) * 2 + aoff * 2));
    __syncwarp();

    // B-frag lane addresses
    // K (QK, non-trans): row = p*16 + (lane&7) + 8*(lane>>4); col = kc*16 + 8*((lane>>3)&1)
    uint32_t kboff = (uint32_t)(((lane & 7) + 8 * (lane >> 4)) * HPAD + 8 * ((lane >> 3) & 1));
    // V (PV, trans): row = kc*16 + (lane&7) + 8*((lane>>3)&1); col = d + 8*(lane>>4)
    uint32_t vboff = (uint32_t)(((lane & 7) + 8 * ((lane >> 3) & 1)) * HPAD + 8 * (lane >> 4));

    float o[2][8][4];
    #pragma unroll
    for (int qb = 0; qb < 2; qb++)
        #pragma unroll
        for (int j = 0; j < 8; j++)
            #pragma unroll
            for (int r = 0; r < 4; r++) o[qb][j][r] = 0.f;
    float lsum[2][2] = {{0.f, 0.f}, {0.f, 0.f}};

    for (int kt = 0; kt < SEQ; kt += 64) {
        __syncthreads();
        // K and V tiles -> smem [key][dim] fp16 (128B rows)
        #pragma unroll
        for (int i = 0; i < 4; i++) {
            int li = i * 128 + tid;
            int row = li >> 3, c8 = li & 7;
            cp16(sb + (uint32_t)((HKS + row * HPAD + c8 * 8) * 2),
                 Kb + (size_t)(kt + row) * LD + c8 * 8);
            cp16(sb + (uint32_t)((HVS + row * HPAD + c8 * 8) * 2),
                 Vb + (size_t)(kt + row) * LD + c8 * 8);
        }
        CP_COMMIT();
        if (tid < 64)
            madd[tid] = (mask[b * SEQ + kt + tid] == 0) ? -1e9f : 0.f;
        CP_WAIT0();
        __syncthreads();

        // ---- S = Q K^T ----
        float s[2][8][4];
        #pragma unroll
        for (int qb = 0; qb < 2; qb++)
            #pragma unroll
            for (int j = 0; j < 8; j++)
                #pragma unroll
                for (int r = 0; r < 4; r++) s[qb][j][r] = 0.f;
        #pragma unroll
        for (int kc = 0; kc < 4; kc++) {
            #pragma unroll
            for (int p = 0; p < 4; p++) {   // p = 16-key group
                uint32_t br[4];
                LDSM4(br, sb + (uint32_t)((HKS + p * 16 * HPAD + kc * 16) * 2 + kboff * 2));
                mma_f16(s[0][2*p],     qa[0][kc], &br[0]);
                mma_f16(s[0][2*p + 1], qa[0][kc], &br[2]);
                mma_f16(s[1][2*p],     qa[1][kc], &br[0]);
                mma_f16(s[1][2*p + 1], qa[1][kc], &br[2]);
            }
        }

        // ---- mask + exp + P(fp16) to smem ----
        #pragma unroll
        for (int qb = 0; qb < 2; qb++) {
            uint32_t pb = pw_half + qb * 16 * HPAD;
            #pragma unroll
            for (int j = 0; j < 8; j++) {
                float md0 = madd[j * 8 + 2 * gc];
                float md1 = madd[j * 8 + 2 * gc + 1];
                float e0 = __expf(s[qb][j][0] + md0);
                float e1 = __expf(s[qb][j][1] + md1);
                float e2 = __expf(s[qb][j][2] + md0);
                float e3 = __expf(s[qb][j][3] + md1);
                lsum[qb][0] += e0 + e1;
                lsum[qb][1] += e2 + e3;
                __half2* p0 = (__half2*)(smh + pb + gr * HPAD + j * 8 + 2 * gc);
                __half2* p1 = (__half2*)(smh + pb + (gr + 8) * HPAD + j * 8 + 2 * gc);
                *p0 = __floats2half2_rn(e0, e1);
                *p1 = __floats2half2_rn(e2, e3);
            }
        }
        __syncwarp();

        // ---- O += P V ----
        #pragma unroll
        for (int kc = 0; kc < 4; kc++) {   // kc = 16-key group
            uint32_t pa0[4], pa1[4];
            LDSM4(pa0, sb + (uint32_t)((pw_half + kc * 16) * 2 + aoff * 2));
            LDSM4(pa1, sb + (uint32_t)((pw_half + 16 * HPAD + kc * 16) * 2 + aoff * 2));
            #pragma unroll
            for (int d = 0; d < 4; d++) {  // d = 16-dim group
                uint32_t br[4];
                LDSM4T(br, sb + (uint32_t)((HVS + kc * 16 * HPAD + d * 16) * 2 + vboff * 2));
                mma_f16(o[0][2*d],     pa0, &br[0]);
                mma_f16(o[0][2*d + 1], pa0, &br[2]);
                mma_f16(o[1][2*d],     pa1, &br[0]);
                mma_f16(o[1][2*d + 1], pa1, &br[2]);
            }
        }
        __syncwarp();
    }

    // ---- row-sum reduction, normalize + store ----
    #pragma unroll
    for (int qb = 0; qb < 2; qb++)
        #pragma unroll
        for (int off = 1; off <= 2; off <<= 1) {
            lsum[qb][0] += __shfl_xor_sync(0xffffffffu, lsum[qb][0], off);
            lsum[qb][1] += __shfl_xor_sync(0xffffffffu, lsum[qb][1], off);
        }
    float* Ob = O + ((size_t)b * SEQ + q0) * DMODEL + hh * DKH;
    #pragma unroll
    for (int qb = 0; qb < 2; qb++) {
        float inv0 = 1.f / lsum[qb][0], inv1 = 1.f / lsum[qb][1];
        int r0 = wrow + qb * 16 + gr;
        #pragma unroll
        for (int j = 0; j < 8; j++) {
            int col = j * 8 + 2 * gc;
            float2 v0 = {o[qb][j][0] * inv0, o[qb][j][1] * inv0};
            float2 v1 = {o[qb][j][2] * inv1, o[qb][j][3] * inv1};
            *(float2*)&Ob[(size_t)r0 * DMODEL + col] = v0;
            *(float2*)&Ob[(size_t)(r0 + 8) * DMODEL + col] = v1;
        }
    }
}

// ================= launch =================
extern "C" void kernel_launch(void* const* d_in, const int* in_sizes, int n_in,
                              void* d_out, int out_size) {
    const float* x    = (const float*)d_in[0];
    const int*   mask = (const int*)  d_in[1];
    const float* wq = (const float*)d_in[2];  const float* bq = (const float*)d_in[3];
    const float* wk = (const float*)d_in[4];  const float* bk = (const float*)d_in[5];
    const float* wv = (const float*)d_in[6];  const float* bv = (const float*)d_in[7];
    const float* wo = (const float*)d_in[8];  const float* bo = (const float*)d_in[9];
    const float* w1 = (const float*)d_in[10]; const float* b1 = (const float*)d_in[11];
    const float* w2 = (const float*)d_in[12]; const float* b2 = (const float*)d_in[13];
    const float* a1 = (const float*)d_in[14]; const float* g1 = (const float*)d_in[15];
    const float* a2 = (const float*)d_in[16]; const float* g2 = (const float*)d_in[17];
    float* out = (float*)d_out;

    float *h, *ctx, *x1, *h2, *ff;
    __half* qkvh;
    cudaGetSymbolAddress((void**)&h,    g_h);
    cudaGetSymbolAddress((void**)&qkvh, g_qkvh);
    cudaGetSymbolAddress((void**)&ctx,  g_ctx);
    cudaGetSymbolAddress((void**)&x1,   g_x1);
    cudaGetSymbolAddress((void**)&h2,   g_h2);
    cudaGetSymbolAddress((void**)&ff,   g_ff);

    cudaFuncSetAttribute(qkv_gemm,      cudaFuncAttributeMaxDynamicSharedMemorySize, GEMM_SMEM);
    cudaFuncSetAttribute(gemm_mma<0,1>, cudaFuncAttributeMaxDynamicSharedMemorySize, GEMM_SMEM);
    cudaFuncSetAttribute(gemm_mma<1,0>, cudaFuncAttributeMaxDynamicSharedMemorySize, GEMM_SMEM);
    cudaFuncSetAttribute(attn_mma, cudaFuncAttributeMaxDynamicSharedMemorySize, ATTN_SMEM);

    // LN1 (warp per row)
    ln_k<<<MROWS / 4, 128>>>(x, h, a1, g1);

    // fused QKV projection -> fp16 (q scaled by 1/8)
    dim3 gqkv(QKVN / 128, MROWS / 128);
    qkv_gemm<<<gqkv, 256, GEMM_SMEM>>>(h, wq, wk, wv, bq, bk, bv, qkvh);

    // attention (fp16 mma)
    dim3 ga(NB * NH, SEQ / 128);
    attn_mma<<<ga, 128, ATTN_SMEM>>>(qkvh, mask, ctx);

    // output projection + residual
    dim3 gp(DMODEL / 128, MROWS / 128);
    gemm_mma<0,1><<<gp, 256, GEMM_SMEM>>>(ctx, wo, bo, x, x1, MROWS, DMODEL, DMODEL);

    // LN2
    ln_k<<<MROWS / 4, 128>>>(x1, h2, a2, g2);

    // FFN
    dim3 gf1(FDIM / 128, MROWS / 128);
    gemm_mma<1,0><<<gf1, 256, GEMM_SMEM>>>(h2, w1, b1, nullptr, ff, MROWS, FDIM, DMODEL);
    gemm_mma<0,1><<<gp, 256, GEMM_SMEM>>>(ff, w2, b2, x1, out, MROWS, DMODEL, FDIM);
}